// round 6
// baseline (speedup 1.0000x reference)
#include <cuda_runtime.h>
#include <cstdint>

// ---------------------------------------------------------------------------
// TractBundle: 3 masked linears (A: 4096->1024 @64 conn, B: 4096->512 @64,
// C: 2048->512 @32), concat on last dim. B=8, S=1024 -> 8192 tokens.
// Sparse gather-FMA. R6 == R5 with the compute() accumulator argument-binding
// bug fixed: (row0_lo, row0_hi, row1_lo, row1_hi).
// ---------------------------------------------------------------------------

#define NROWS      2048
#define ROWCAP     96          // entries per row (max 64 + per-slice padding)
#define RQ         (ROWCAP/4)  // 24 quads per row
#define SLICE      512
#define XSTR       513         // odd stride -> conflict-free gathers
#define NTOK       64
#define TPB        512         // 16 warps
#define RPW        32          // rows per warp (16 pairs)
#define SM_X_BYTES (NTOK * XSTR * 4)            // 131328
#define SM_SCR_OFF SM_X_BYTES                   // 16 warps * 2 slots * 1024 B
#define SMEM_BYTES (SM_SCR_OFF + 16 * 2048)     // 164096

__device__ __align__(16) int   g_idx[NROWS * ROWCAP];   // byte offsets within slice
__device__ __align__(16) float g_w  [NROWS * ROWCAP];
__device__ __align__(8)  unsigned g_seg[8 * NROWS];     // [slice][row]: qstart | (nq<<16), quads

// ---------------------------------------------------------------------------
// Prep: one warp per dst row; ballot-compact nonzeros (ascending), w*m,
// pad each slice segment to a multiple of 4 entries.
// ---------------------------------------------------------------------------
__global__ void prep_kernel(const float* __restrict__ wa, const float* __restrict__ ma,
                            const float* __restrict__ wb, const float* __restrict__ mb,
                            const float* __restrict__ wc, const float* __restrict__ mc)
{
    int gw   = (blockIdx.x * blockDim.x + threadIdx.x) >> 5;
    int lane = threadIdx.x & 31;
    if (gw >= NROWS) return;

    const float *w, *m; int nsl;
    if (gw < 1024)      { w = wa + (size_t)gw * 4096;        m = ma + (size_t)gw * 4096;        nsl = 8; }
    else if (gw < 1536) { w = wb + (size_t)(gw-1024) * 4096; m = mb + (size_t)(gw-1024) * 4096; nsl = 8; }
    else                { w = wc + (size_t)(gw-1536) * 2048; m = mc + (size_t)(gw-1536) * 2048; nsl = 4; }

    int base = gw * ROWCAP;
    int cnt  = 0;
    unsigned ltmask = (1u << lane) - 1u;

    for (int k = 0; k < 8; k++) {
        if (k >= nsl) {
            if (lane == 0) g_seg[k * NROWS + gw] = (unsigned)(cnt >> 2);
            continue;
        }
        int start = cnt;
        for (int c = 0; c < SLICE; c += 32) {
            int   s  = k * SLICE + c + lane;
            float mv = m[s];
            bool  p  = (mv != 0.0f);
            unsigned b = __ballot_sync(0xffffffffu, p);
            if (p) {
                int pos = cnt + __popc(b & ltmask);
                g_idx[base + pos] = (c + lane) * 4;
                g_w  [base + pos] = w[s] * mv;
            }
            cnt += __popc(b);
        }
        int n    = cnt - start;
        int npad = (n + 3) & ~3;
        if (lane < npad - n) {
            g_idx[base + cnt + lane] = 0;
            g_w  [base + cnt + lane] = 0.0f;
        }
        cnt = start + npad;
        if (lane == 0)
            g_seg[k * NROWS + gw] = (unsigned)(start >> 2) | ((unsigned)(npad >> 2) << 16);
    }
}

__device__ __forceinline__ uint32_t smem_u32(const void* p) {
    uint32_t a;
    asm("{ .reg .u64 t; cvta.to.shared.u64 t, %1; cvt.u32.u64 %0, t; }" : "=r"(a) : "l"(p));
    return a;
}

// ---------------------------------------------------------------------------
// Gather kernel. Grid: (128 token tiles of 64, 4 row groups of 512 rows).
// Block: 512 threads / 16 warps; warp owns 32 rows (16 pairs, fully unrolled).
// Lane l <-> tokens t0+l and t0+32+l.
// ---------------------------------------------------------------------------
__global__ void __launch_bounds__(TPB, 1)
gather_kernel(const float* __restrict__ xa, const float* __restrict__ xb,
              const float* __restrict__ xc, float* __restrict__ out)
{
    extern __shared__ char smc[];
    float* sm = (float*)smc;

    const int grp = blockIdx.y;
    const int t0  = blockIdx.x * NTOK;

    const float* x; int S, nsl, row0g;
    if (grp <= 1)      { x = xa; S = 4096; nsl = 8; row0g = grp * 512; }
    else if (grp == 2) { x = xb; S = 4096; nsl = 8; row0g = 1024; }
    else               { x = xc; S = 2048; nsl = 4; row0g = 1536; }

    const int tid    = threadIdx.x;
    const int lane   = tid & 31;
    const int warp   = tid >> 5;
    const int half   = lane >> 4;
    const int lh     = lane & 15;
    const int myrow0 = row0g + warp * RPW;

    float acc[2 * RPW];
#pragma unroll
    for (int r = 0; r < 2 * RPW; r++) acc[r] = 0.0f;

    const uint32_t sm_base = smem_u32(smc);
    const uint32_t xlo = sm_base + (uint32_t)(lane * XSTR) * 4u;
    const uint32_t xhi = xlo + 32u * XSTR * 4u;
    const uint32_t scr = sm_base + SM_SCR_OFF + (uint32_t)warp * 2048u;  // + slot*1024
    const uint32_t d_i = scr + (uint32_t)lane * 16u;        // idx quad dest (+slot*1024)
    const uint32_t d_w = scr + 512u + (uint32_t)lane * 16u; // w quad dest

    // preload issue: half-warp h handles row (pair*2 + h); lane lh <-> quad lh
    auto issue = [&](uint2 sp, int pr, int slot) {
        unsigned sh = half ? sp.y : sp.x;
        int nqh  = (int)(sh >> 16);
        int qoff = (lh < nqh) ? lh : (nqh > 0 ? nqh - 1 : 0);
        int qidx = (myrow0 + 2 * pr + half) * RQ + (int)(sh & 0xffffu) + qoff;
        const int4*   si = (const int4*)g_idx + qidx;
        const float4* sw = (const float4*)g_w + qidx;
        uint32_t off = (uint32_t)slot * 1024u;
        asm volatile("cp.async.ca.shared.global [%0], [%1], 16;\n" :: "r"(d_i + off), "l"(si) : "memory");
        asm volatile("cp.async.ca.shared.global [%0], [%1], 16;\n" :: "r"(d_w + off), "l"(sw) : "memory");
        asm volatile("cp.async.commit_group;\n" ::: "memory");
    };

    // a0l/a0h: row0 low/high token; a1l/a1h: row1 low/high token
    auto compute = [&](uint2 sp, int slot, float& a0l, float& a0h, float& a1l, float& a1h) {
        int nq0 = (int)(sp.x >> 16);
        int nq1 = (int)(sp.y >> 16);
        int mq  = nq0 > nq1 ? nq0 : nq1;
        const char* b = smc + SM_SCR_OFF + warp * 2048 + slot * 1024;
        const int4*   qi = (const int4*)b;            // [0:16) row0, [16:32) row1
        const float4* qw = (const float4*)(b + 512);
        for (int q = 0; q < mq; q++) {
            int4   i0 = qi[q];
            float4 w0 = qw[q];
            int4   i1 = qi[16 + q];
            float4 w1 = qw[16 + q];
            if (q < nq0) {
                float u0,u1,u2,u3, v0,v1,v2,v3;
                asm volatile("ld.shared.f32 %0, [%1];" : "=f"(u0) : "r"(xlo + (uint32_t)i0.x));
                asm volatile("ld.shared.f32 %0, [%1];" : "=f"(u1) : "r"(xlo + (uint32_t)i0.y));
                asm volatile("ld.shared.f32 %0, [%1];" : "=f"(u2) : "r"(xlo + (uint32_t)i0.z));
                asm volatile("ld.shared.f32 %0, [%1];" : "=f"(u3) : "r"(xlo + (uint32_t)i0.w));
                asm volatile("ld.shared.f32 %0, [%1];" : "=f"(v0) : "r"(xhi + (uint32_t)i0.x));
                asm volatile("ld.shared.f32 %0, [%1];" : "=f"(v1) : "r"(xhi + (uint32_t)i0.y));
                asm volatile("ld.shared.f32 %0, [%1];" : "=f"(v2) : "r"(xhi + (uint32_t)i0.z));
                asm volatile("ld.shared.f32 %0, [%1];" : "=f"(v3) : "r"(xhi + (uint32_t)i0.w));
                float p0 = fmaf(u1, w0.y, u0 * w0.x);
                float p1 = fmaf(u3, w0.w, u2 * w0.z);
                a0l = (a0l + p0) + p1;
                float r0 = fmaf(v1, w0.y, v0 * w0.x);
                float r1 = fmaf(v3, w0.w, v2 * w0.z);
                a0h = (a0h + r0) + r1;
            }
            if (q < nq1) {
                float u0,u1,u2,u3, v0,v1,v2,v3;
                asm volatile("ld.shared.f32 %0, [%1];" : "=f"(u0) : "r"(xlo + (uint32_t)i1.x));
                asm volatile("ld.shared.f32 %0, [%1];" : "=f"(u1) : "r"(xlo + (uint32_t)i1.y));
                asm volatile("ld.shared.f32 %0, [%1];" : "=f"(u2) : "r"(xlo + (uint32_t)i1.z));
                asm volatile("ld.shared.f32 %0, [%1];" : "=f"(u3) : "r"(xlo + (uint32_t)i1.w));
                asm volatile("ld.shared.f32 %0, [%1];" : "=f"(v0) : "r"(xhi + (uint32_t)i1.x));
                asm volatile("ld.shared.f32 %0, [%1];" : "=f"(v1) : "r"(xhi + (uint32_t)i1.y));
                asm volatile("ld.shared.f32 %0, [%1];" : "=f"(v2) : "r"(xhi + (uint32_t)i1.z));
                asm volatile("ld.shared.f32 %0, [%1];" : "=f"(v3) : "r"(xhi + (uint32_t)i1.w));
                float p0 = fmaf(u1, w1.y, u0 * w1.x);
                float p1 = fmaf(u3, w1.w, u2 * w1.z);
                a1l = (a1l + p0) + p1;
                float r0 = fmaf(v1, w1.y, v0 * w1.x);
                float r1 = fmaf(v3, w1.w, v2 * w1.z);
                a1h = (a1h + r0) + r1;
            }
        }
    };

    for (int k = 0; k < nsl; k++) {
        if (k) __syncthreads();

        // --- stage 64 tokens x 512 cols, 4B cp.async, conflict-free ---
        {
            const float* src = x + (size_t)t0 * S + k * SLICE + tid;
            uint32_t dst = sm_base + (uint32_t)tid * 4u;
#pragma unroll
            for (int it = 0; it < NTOK; it++) {
                asm volatile("cp.async.ca.shared.global [%0], [%1], 4;\n"
                             :: "r"(dst), "l"(src) : "memory");
                dst += XSTR * 4;
                src += S;
            }
        }
        asm volatile("cp.async.commit_group;\n" ::: "memory");
        asm volatile("cp.async.wait_group 0;\n" ::: "memory");
        __syncthreads();

        const unsigned* segk = g_seg + k * NROWS + myrow0;

        uint2 segc = *(const uint2*)segk;
        issue(segc, 0, 0);

#pragma unroll
        for (int p = 0; p < RPW / 2; p++) {
            uint2 segn = segc;
            __syncwarp();                       // slot (p+1)&1 reads (pair p-1) done
            if (p < RPW / 2 - 1) {
                segn = *(const uint2*)(segk + 2 * (p + 1));
                issue(segn, p + 1, (p + 1) & 1);
                asm volatile("cp.async.wait_group 1;\n" ::: "memory");
            } else {
                asm volatile("cp.async.wait_group 0;\n" ::: "memory");
            }
            __syncwarp();                       // pair p's quads visible warp-wide
            // FIX: bind (row0_lo, row0_hi, row1_lo, row1_hi)
            compute(segc, p & 1,
                    acc[2*p],       acc[RPW + 2*p],
                    acc[2*p + 1],   acc[RPW + 2*p + 1]);
            segc = segn;
        }
    }

    // --- epilogue: per-warp smem transpose -> coalesced STG, both token halves ---
    __syncthreads();
    float* tw = sm + warp * (32 * 33);
#pragma unroll
    for (int r = 0; r < RPW; r++) tw[lane * 33 + r] = acc[r];
    __syncwarp();
#pragma unroll
    for (int tt = 0; tt < 32; tt++)
        out[(size_t)(t0 + tt) * 2048 + myrow0 + lane] = tw[tt * 33 + lane];
    __syncwarp();
#pragma unroll
    for (int r = 0; r < RPW; r++) tw[lane * 33 + r] = acc[RPW + r];
    __syncwarp();
#pragma unroll
    for (int tt = 0; tt < 32; tt++)
        out[(size_t)(t0 + 32 + tt) * 2048 + myrow0 + lane] = tw[tt * 33 + lane];
}

// ---------------------------------------------------------------------------
extern "C" void kernel_launch(void* const* d_in, const int* in_sizes, int n_in,
                              void* d_out, int out_size)
{
    const float *x_a, *w_a, *m_a, *x_b, *w_b, *m_b, *x_c, *w_c, *m_c;
    if (n_in >= 9 && in_sizes[1] == 4194304) {
        x_a = (const float*)d_in[0]; w_a = (const float*)d_in[1]; m_a = (const float*)d_in[2];
        x_b = (const float*)d_in[3]; w_b = (const float*)d_in[4]; m_b = (const float*)d_in[5];
        x_c = (const float*)d_in[6]; w_c = (const float*)d_in[7]; m_c = (const float*)d_in[8];
    } else {
        x_a = (const float*)d_in[0]; x_b = (const float*)d_in[1]; x_c = (const float*)d_in[2];
        w_a = (const float*)d_in[3]; w_b = (const float*)d_in[4]; w_c = (const float*)d_in[5];
        m_a = (const float*)d_in[6]; m_b = (const float*)d_in[7]; m_c = (const float*)d_in[8];
    }

    float* out = (float*)d_out;

    static int attr_done = 0;
    if (!attr_done) {
        cudaFuncSetAttribute(gather_kernel, cudaFuncAttributeMaxDynamicSharedMemorySize, SMEM_BYTES);
        attr_done = 1;
    }

    prep_kernel<<<NROWS / 8, 256>>>(w_a, m_a, w_b, m_b, w_c, m_c);

    dim3 grid(8192 / NTOK, 4);
    gather_kernel<<<grid, TPB, SMEM_BYTES>>>(x_a, x_b, x_c, out);
}